// round 5
// baseline (speedup 1.0000x reference)
#include <cuda_runtime.h>
#include <cuda_bf16.h>
#include <cstdint>

// SpatiallyJitterColorChannels: per-(b,c) 2D roll of x[64,3,512,512] fp32.
// out[b,c,h,w] = x[b,c,(h-sh)&511,(w-sw)&511], sh/sw = shifts[b,c,:]-2, |s|<=2.
//
// R5: measured-best R2 configuration + write-through streaming stores.
//  - dual adjacent aligned LDG.128 per output quad (B quad of thread t is
//    A quad of thread t+1 -> L1 hit, free; proven in R2/R3).
//  - register select by per-plane-uniform offset o in {0..3}.
//  - __stwt stores: avoid accumulating 192MB of dirty L2 lines whose burst
//    writebacks compete with read fills (only untested memory-policy axis;
//    R2=default and R4=.cs both plateaued at ~6.2TB/s).
//  - ILP=2, 256 threads, 24576 blocks (occ ~85%, the best-measured shape).

#define SHIFT 2

__global__ void __launch_bounds__(256) roll2d_kernel(
    const float* __restrict__ x,
    const int*   __restrict__ shifts,   // [B, C, 2] int32 in [0, 2*SHIFT]
    float*       __restrict__ out)
{
    int base  = blockIdx.x * 512 + threadIdx.x;   // float4 index of element 0
    int plane = base >> 16;                       // / 65536 f4 per plane

    int sh = shifts[plane * 2 + 0] - SHIFT;
    int sw = shifts[plane * 2 + 1] - SHIFT;

    int qa_off = (sw > 0) ? -4 : 0;
    int o      = (sw > 0) ? 4 - sw : -sw;         // select offset, 0..3

    const float* planep = x + ((size_t)plane << 18);   // * 262144
    float4* out4 = reinterpret_cast<float4*>(out);

    float4 A[2], B[2];
    int    oidx[2];

    #pragma unroll
    for (int e = 0; e < 2; e++) {
        int idx    = base + e * 256;
        int within = idx & 65535;
        int h      = within >> 7;            // 128 f4 per row
        int w0     = (within & 127) << 2;
        int hs     = (h - sh) & 511;
        const float* rowp = planep + (hs << 9);
        int qa = (w0 + qa_off) & 511;        // aligned quad, in-row wrap
        int qb = (qa + 4) & 511;
        A[e] = *reinterpret_cast<const float4*>(rowp + qa);
        B[e] = *reinterpret_cast<const float4*>(rowp + qb);
        oidx[e] = idx;
    }

    #pragma unroll
    for (int e = 0; e < 2; e++) {
        float4 v;
        switch (o) {   // uniform per plane -> no divergence
            case 0:  v = A[e]; break;
            case 1:  v = make_float4(A[e].y, A[e].z, A[e].w, B[e].x); break;
            case 2:  v = make_float4(A[e].z, A[e].w, B[e].x, B[e].y); break;
            default: v = make_float4(A[e].w, B[e].x, B[e].y, B[e].z); break;
        }
        __stwt(out4 + oidx[e], v);           // write-through streaming store
    }
}

extern "C" void kernel_launch(void* const* d_in, const int* in_sizes, int n_in,
                              void* d_out, int out_size)
{
    const float* x      = (const float*)d_in[0];
    const int*   shifts = (const int*)d_in[1];
    float*       out    = (float*)d_out;

    int n_f4   = out_size / 4;               // 12582912
    int blocks = n_f4 / 512;                 // 24576
    roll2d_kernel<<<blocks, 256>>>(x, shifts, out);
}